// round 9
// baseline (speedup 1.0000x reference)
#include <cuda_runtime.h>

#define FM_H 38
#define FM_W 50
#define N_ROI 512
#define POOL 7

__device__ __forceinline__ float4 quad4(float4 a, float4 b, float4 c, float4 d,
                                        float w0, float w1, float w2, float w3) {
    float4 r;
    r.x = fmaf(d.x, w3, fmaf(c.x, w2, fmaf(b.x, w1, a.x * w0)));
    r.y = fmaf(d.y, w3, fmaf(c.y, w2, fmaf(b.y, w1, a.y * w0)));
    r.z = fmaf(d.z, w3, fmaf(c.z, w2, fmaf(b.z, w1, a.z * w0)));
    r.w = fmaf(d.w, w3, fmaf(c.w, w2, fmaf(b.w, w1, a.w * w0)));
    return r;
}

__device__ __forceinline__ float4 max4(float4 a, float4 b) {
    float4 r;
    r.x = fmaxf(a.x, b.x);
    r.y = fmaxf(a.y, b.y);
    r.z = fmaxf(a.z, b.z);
    r.w = fmaxf(a.w, b.w);
    return r;
}

// MODE 0: 2 distinct fm rows (r0,r1); pair-b reuses them via folded weights.
// MODE 1: 3 rows, pair-b reads (r1,r2). MODE 2: 4 rows, pair-b reads (r2,r3).
// Columns: x0a,x1a loaded unconditionally; x0b / x1b columns loaded under
// single-instruction predicates (no BSSY -> cross-cell batching preserved),
// defaults taken from already-loaded registers. Straight-line over 7 cells.
template <int MODE>
__device__ __forceinline__ void run_row(
    const float4* __restrict__ fmt, float4* __restrict__ outp,
    float x1n, float dx,
    int r0, int r1, int r2, int r3,
    float waP, float waQ,      // row weights for pair a (rows r0,r1)
    float wbP, float wbQ)      // row weights for pair b (rows per MODE)
{
    constexpr int NR = (MODE == 0) ? 2 : (MODE == 1) ? 3 : 4;
    constexpr int PB = (MODE == 0) ? 0 : (MODE == 1) ? 1 : 2;
    int ro[4] = {r0, r1, r2, r3};

#pragma unroll
    for (int px = 0; px < POOL; ++px) {
        // x taps for the two crop cols of this pooled cell (block-uniform)
        int x0a, x1a, x0b, x1b;
        float wxa, wxb;
        {
            const float txa = (float)(2 * px) * (1.0f / 13.0f);
            const float xsa = (x1n + txa * dx) * (float)(FM_W - 1);
            const float xfa = floorf(xsa);
            int x0 = (int)xfa; x0 = min(max(x0, 0), FM_W - 1);
            x0a = x0; x1a = min(x0 + 1, FM_W - 1); wxa = xsa - xfa;

            const float txb = (float)(2 * px + 1) * (1.0f / 13.0f);
            const float xsb = (x1n + txb * dx) * (float)(FM_W - 1);
            const float xfb = floorf(xsb);
            int x1 = (int)xfb; x1 = min(max(x1, 0), FM_W - 1);
            x0b = x1; x1b = min(x0b + 1, FM_W - 1); wxb = xsb - xfb;
        }
        const float uxa = 1.0f - wxa;
        const float uxb = 1.0f - wxb;

        // Column-dup predicates (block-uniform, branch-free)
        const bool n2   = (x0b > x1a);   // pair-b left col is a new column
        const bool n3   = (x0b > x0a);   // pair-b right col is a new column
        const bool dupA = (x0b == x0a);  // pair-b left col == x0a

        // G[r][c]: c0=x0a, c1=x1a, c2=x0b-col, c3=x1b-col
        float4 G[NR][4];
#pragma unroll
        for (int r = 0; r < NR; ++r) {
            G[r][0] = fmt[(ro[r] + x0a) * 128];
            G[r][1] = fmt[(ro[r] + x1a) * 128];
        }
#pragma unroll
        for (int r = 0; r < NR; ++r) {
            // default: duplicate of an already-loaded column
            float4 v2;
            v2.x = dupA ? G[r][0].x : G[r][1].x;
            v2.y = dupA ? G[r][0].y : G[r][1].y;
            v2.z = dupA ? G[r][0].z : G[r][1].z;
            v2.w = dupA ? G[r][0].w : G[r][1].w;
            if (n2) v2 = fmt[(ro[r] + x0b) * 128];   // single predicated LDG
            G[r][2] = v2;

            float4 v3 = G[r][1];                     // x1b==x1a when !n3
            if (n3) v3 = fmt[(ro[r] + x1b) * 128];   // single predicated LDG
            G[r][3] = v3;
        }

        const float4 s_aa = quad4(G[0][0], G[0][1], G[1][0], G[1][1],
                                  waP * uxa, waP * wxa, waQ * uxa, waQ * wxa);
        const float4 s_ab = quad4(G[0][2], G[0][3], G[1][2], G[1][3],
                                  waP * uxb, waP * wxb, waQ * uxb, waQ * wxb);
        const float4 s_ba = quad4(G[PB][0], G[PB][1], G[PB + 1][0], G[PB + 1][1],
                                  wbP * uxa, wbP * wxa, wbQ * uxa, wbQ * wxa);
        const float4 s_bb = quad4(G[PB][2], G[PB][3], G[PB + 1][2], G[PB + 1][3],
                                  wbP * uxb, wbP * wxb, wbQ * uxb, wbQ * wxb);

        outp[px * 128] = max4(max4(s_aa, s_ab), max4(s_ba, s_bb));
    }
}

// One block per (pooled_row, roi). 128 threads x float4 = 512 channels.
// Row-tap dedup via ONE block-uniform dispatch; column-tap dedup via
// predicated loads inside the branch-free cell loop.
__global__ __launch_bounds__(128) void roi_pool_kernel(
    const float* __restrict__ fm,     // [38,50,512]
    const float* __restrict__ rois,   // [512,5] (0, x1, y1, x2, y2)
    float* __restrict__ out)          // [512,7,7,512]
{
    const int py  = blockIdx.x;       // 0..6
    const int roi = blockIdx.y;       // 0..511
    const int t   = threadIdx.x;      // channel group: c = 4*t

    const float* r = rois + roi * 5;
    const float x1n = r[1] * (1.0f / 800.0f);
    const float y1n = r[2] * (1.0f / 600.0f);
    const float x2n = r[3] * (1.0f / 800.0f);
    const float y2n = r[4] * (1.0f / 600.0f);
    const float dy = y2n - y1n;
    const float dx = x2n - x1n;

    // y taps for the two crop rows of this pooled row (block-uniform)
    int ra0, ra1, rb0, rb1;           // fm row offsets (row * FM_W)
    float wya, wyb;
    {
        const float tya = (float)(2 * py) * (1.0f / 13.0f);
        const float ysa = (y1n + tya * dy) * (float)(FM_H - 1);
        const float yfa = floorf(ysa);
        int y0 = (int)yfa; y0 = min(max(y0, 0), FM_H - 1);
        ra0 = y0 * FM_W;
        ra1 = min(y0 + 1, FM_H - 1) * FM_W;
        wya = ysa - yfa;

        const float tyb = (float)(2 * py + 1) * (1.0f / 13.0f);
        const float ysb = (y1n + tyb * dy) * (float)(FM_H - 1);
        const float yfb = floorf(ysb);
        int y1 = (int)yfb; y1 = min(max(y1, 0), FM_H - 1);
        rb0 = y1 * FM_W;
        rb1 = min(y1 + 1, FM_H - 1) * FM_W;
        wyb = ysb - yfb;
    }
    const float uya = 1.0f - wya;
    const float uyb = 1.0f - wyb;

    const float4* fmt = (const float4*)fm + t;
    float4* outp = (float4*)out + (size_t)((roi * POOL + py) * POOL) * 128 + t;

    // Row dedup dispatch (block-uniform branch, fixed for all 7 cells).
    if (rb0 == ra0) {
        run_row<0>(fmt, outp, x1n, dx, ra0, ra1, 0, 0,
                   uya, wya, uyb, wyb);
    } else if (rb0 == ra1) {
        if (rb1 == rb0) {
            run_row<0>(fmt, outp, x1n, dx, ra0, ra1, 0, 0,
                       uya, wya, 0.0f, uyb + wyb);
        } else {
            run_row<1>(fmt, outp, x1n, dx, ra0, ra1, rb1, 0,
                       uya, wya, uyb, wyb);
        }
    } else {
        run_row<2>(fmt, outp, x1n, dx, ra0, ra1, rb0, rb1,
                   uya, wya, uyb, wyb);
    }
}

extern "C" void kernel_launch(void* const* d_in, const int* in_sizes, int n_in,
                              void* d_out, int out_size)
{
    const float* fm   = (const float*)d_in[0];   // feature_maps [1,38,50,512]
    const float* rois = (const float*)d_in[1];   // [512,5]
    float* out = (float*)d_out;                  // [1,512,7,7,512]

    dim3 grid(POOL, N_ROI);
    roi_pool_kernel<<<grid, 128>>>(fm, rois, out);
}

// round 10
// speedup vs baseline: 1.6899x; 1.6899x over previous
#include <cuda_runtime.h>
#include <cuda_fp16.h>

#define FM_H 38
#define FM_W 50
#define N_ROI 512
#define POOL 7
#define FM_ELEMS (FM_H * FM_W * 512)

// fp16 copy of the feature map (static scratch; allocation-free).
__device__ __align__(16) static __half g_fmh[FM_ELEMS];

// ---- fp32 -> fp16 convert kernel (cheap: 3.9MB read / 1.9MB write) ----
__global__ __launch_bounds__(256) void convert_kernel(const float* __restrict__ fm) {
    const int i = blockIdx.x * blockDim.x + threadIdx.x;   // one float4 each
    const int n4 = FM_ELEMS / 4;                           // 243200
    if (i < n4) {
        const float4 v = ((const float4*)fm)[i];
        __half2 h0 = __floats2half2_rn(v.x, v.y);
        __half2 h1 = __floats2half2_rn(v.z, v.w);
        uint2 u;
        u.x = *reinterpret_cast<unsigned*>(&h0);
        u.y = *reinterpret_cast<unsigned*>(&h1);
        ((uint2*)g_fmh)[i] = u;
    }
}

// ---- half4 helpers ----
struct h4 { __half2 a, b; };

__device__ __forceinline__ h4 ld_h4(const uint2* __restrict__ p) {
    const uint2 u = *p;                    // single LDG.64
    h4 v;
    v.a = *reinterpret_cast<const __half2*>(&u.x);
    v.b = *reinterpret_cast<const __half2*>(&u.y);
    return v;
}

__device__ __forceinline__ h4 quad4h(h4 A, h4 B, h4 C, h4 D,
                                     __half2 w0, __half2 w1, __half2 w2, __half2 w3) {
    h4 r;
    r.a = __hfma2(D.a, w3, __hfma2(C.a, w2, __hfma2(B.a, w1, __hmul2(A.a, w0))));
    r.b = __hfma2(D.b, w3, __hfma2(C.b, w2, __hfma2(B.b, w1, __hmul2(A.b, w0))));
    return r;
}

__device__ __forceinline__ h4 max4h(h4 x, h4 y) {
    h4 r;
    r.a = __hmax2(x.a, y.a);
    r.b = __hmax2(x.b, y.b);
    return r;
}

// MODE 0: 2 distinct fm rows; pair-b reuses them via folded weights.
// MODE 1: 3 rows, pair-b reads (r1,r2). MODE 2: 4 rows, pair-b reads (r2,r3).
// Exact R5 structure: straight-line over 7 cells, unconditional batched loads.
template <int MODE>
__device__ __forceinline__ void run_row(
    const uint2* __restrict__ fmt, float4* __restrict__ outp,
    float x1n, float dx,
    int r0, int r1, int r2, int r3,
    __half2 hwaP, __half2 hwaQ,    // row weights pair a (rows r0,r1)
    __half2 hwbP, __half2 hwbQ)    // row weights pair b (rows per MODE)
{
#pragma unroll
    for (int px = 0; px < POOL; ++px) {
        // x taps for the two crop cols of this pooled cell (block-uniform, fp32)
        int x0a, x1a, x0b, x1b;
        float wxa, wxb;
        {
            const float txa = (float)(2 * px) * (1.0f / 13.0f);
            const float xsa = (x1n + txa * dx) * (float)(FM_W - 1);
            const float xfa = floorf(xsa);
            int x0 = (int)xfa; x0 = min(max(x0, 0), FM_W - 1);
            x0a = x0; x1a = min(x0 + 1, FM_W - 1); wxa = xsa - xfa;

            const float txb = (float)(2 * px + 1) * (1.0f / 13.0f);
            const float xsb = (x1n + txb * dx) * (float)(FM_W - 1);
            const float xfb = floorf(xsb);
            int x1 = (int)xfb; x1 = min(max(x1, 0), FM_W - 1);
            x0b = x1; x1b = min(x1 + 1, FM_W - 1); wxb = xsb - xfb;
        }
        const __half2 huxa = __float2half2_rn(1.0f - wxa);
        const __half2 hwxa = __float2half2_rn(wxa);
        const __half2 huxb = __float2half2_rn(1.0f - wxb);
        const __half2 hwxb = __float2half2_rn(wxb);

        // Unconditional batched loads: (2 + MODE distinct rows) x 4 cols
        const h4 vA0a = ld_h4(fmt + (r0 + x0a) * 128);
        const h4 vA1a = ld_h4(fmt + (r0 + x1a) * 128);
        const h4 vA0b = ld_h4(fmt + (r0 + x0b) * 128);
        const h4 vA1b = ld_h4(fmt + (r0 + x1b) * 128);
        const h4 vB0a = ld_h4(fmt + (r1 + x0a) * 128);
        const h4 vB1a = ld_h4(fmt + (r1 + x1a) * 128);
        const h4 vB0b = ld_h4(fmt + (r1 + x0b) * 128);
        const h4 vB1b = ld_h4(fmt + (r1 + x1b) * 128);

        h4 vC0a, vC1a, vC0b, vC1b;   // pair-b source row P
        h4 vD0a, vD1a, vD0b, vD1b;   // pair-b source row Q
        if (MODE == 0) {
            vC0a = vA0a; vC1a = vA1a; vC0b = vA0b; vC1b = vA1b;
            vD0a = vB0a; vD1a = vB1a; vD0b = vB0b; vD1b = vB1b;
        } else if (MODE == 1) {
            vC0a = vB0a; vC1a = vB1a; vC0b = vB0b; vC1b = vB1b;
            vD0a = ld_h4(fmt + (r2 + x0a) * 128);
            vD1a = ld_h4(fmt + (r2 + x1a) * 128);
            vD0b = ld_h4(fmt + (r2 + x0b) * 128);
            vD1b = ld_h4(fmt + (r2 + x1b) * 128);
        } else {
            vC0a = ld_h4(fmt + (r2 + x0a) * 128);
            vC1a = ld_h4(fmt + (r2 + x1a) * 128);
            vC0b = ld_h4(fmt + (r2 + x0b) * 128);
            vC1b = ld_h4(fmt + (r2 + x1b) * 128);
            vD0a = ld_h4(fmt + (r3 + x0a) * 128);
            vD1a = ld_h4(fmt + (r3 + x1a) * 128);
            vD0b = ld_h4(fmt + (r3 + x0b) * 128);
            vD1b = ld_h4(fmt + (r3 + x1b) * 128);
        }

        const h4 s_aa = quad4h(vA0a, vA1a, vB0a, vB1a,
                               __hmul2(hwaP, huxa), __hmul2(hwaP, hwxa),
                               __hmul2(hwaQ, huxa), __hmul2(hwaQ, hwxa));
        const h4 s_ab = quad4h(vA0b, vA1b, vB0b, vB1b,
                               __hmul2(hwaP, huxb), __hmul2(hwaP, hwxb),
                               __hmul2(hwaQ, huxb), __hmul2(hwaQ, hwxb));
        const h4 s_ba = quad4h(vC0a, vC1a, vD0a, vD1a,
                               __hmul2(hwbP, huxa), __hmul2(hwbP, hwxa),
                               __hmul2(hwbQ, huxa), __hmul2(hwbQ, hwxa));
        const h4 s_bb = quad4h(vC0b, vC1b, vD0b, vD1b,
                               __hmul2(hwbP, huxb), __hmul2(hwbP, hwxb),
                               __hmul2(hwbQ, huxb), __hmul2(hwbQ, hwxb));

        const h4 m = max4h(max4h(s_aa, s_ab), max4h(s_ba, s_bb));

        const float2 lo = __half22float2(m.a);
        const float2 hi = __half22float2(m.b);
        outp[px * 128] = make_float4(lo.x, lo.y, hi.x, hi.y);
    }
}

// One block per (pooled_row, roi). 128 threads x half4 = 512 channels.
// Row-tap dedup via ONE block-uniform dispatch; cell loop branch-free (R5).
__global__ __launch_bounds__(128) void roi_pool_kernel(
    const float* __restrict__ rois,   // [512,5] (0, x1, y1, x2, y2)
    float* __restrict__ out)          // [512,7,7,512]
{
    const int py  = blockIdx.x;       // 0..6
    const int roi = blockIdx.y;       // 0..511
    const int t   = threadIdx.x;      // channel group: c = 4*t

    const float* r = rois + roi * 5;
    const float x1n = r[1] * (1.0f / 800.0f);
    const float y1n = r[2] * (1.0f / 600.0f);
    const float x2n = r[3] * (1.0f / 800.0f);
    const float y2n = r[4] * (1.0f / 600.0f);
    const float dy = y2n - y1n;
    const float dx = x2n - x1n;

    // y taps for the two crop rows of this pooled row (block-uniform)
    int ra0, ra1, rb0, rb1;           // fm row offsets (row * FM_W)
    float wya, wyb;
    {
        const float tya = (float)(2 * py) * (1.0f / 13.0f);
        const float ysa = (y1n + tya * dy) * (float)(FM_H - 1);
        const float yfa = floorf(ysa);
        int y0 = (int)yfa; y0 = min(max(y0, 0), FM_H - 1);
        ra0 = y0 * FM_W;
        ra1 = min(y0 + 1, FM_H - 1) * FM_W;
        wya = ysa - yfa;

        const float tyb = (float)(2 * py + 1) * (1.0f / 13.0f);
        const float ysb = (y1n + tyb * dy) * (float)(FM_H - 1);
        const float yfb = floorf(ysb);
        int y1 = (int)yfb; y1 = min(max(y1, 0), FM_H - 1);
        rb0 = y1 * FM_W;
        rb1 = min(y1 + 1, FM_H - 1) * FM_W;
        wyb = ysb - yfb;
    }

    const uint2* fmt = (const uint2*)g_fmh + t;
    float4* outp = (float4*)out + (size_t)((roi * POOL + py) * POOL) * 128 + t;

    const __half2 hwya = __float2half2_rn(wya);
    const __half2 huya = __float2half2_rn(1.0f - wya);
    const __half2 hwyb = __float2half2_rn(wyb);
    const __half2 huyb = __float2half2_rn(1.0f - wyb);

    // Row dedup dispatch (block-uniform branch, fixed for all 7 cells).
    if (rb0 == ra0) {
        run_row<0>(fmt, outp, x1n, dx, ra0, ra1, 0, 0,
                   huya, hwya, huyb, hwyb);
    } else if (rb0 == ra1) {
        if (rb1 == rb0) {
            run_row<0>(fmt, outp, x1n, dx, ra0, ra1, 0, 0,
                       huya, hwya, __float2half2_rn(0.0f), __float2half2_rn(1.0f));
        } else {
            run_row<1>(fmt, outp, x1n, dx, ra0, ra1, rb1, 0,
                       huya, hwya, huyb, hwyb);
        }
    } else {
        run_row<2>(fmt, outp, x1n, dx, ra0, ra1, rb0, rb1,
                   huya, hwya, huyb, hwyb);
    }
}

extern "C" void kernel_launch(void* const* d_in, const int* in_sizes, int n_in,
                              void* d_out, int out_size)
{
    const float* fm   = (const float*)d_in[0];   // feature_maps [1,38,50,512]
    const float* rois = (const float*)d_in[1];   // [512,5]
    float* out = (float*)d_out;                  // [1,512,7,7,512]

    const int n4 = FM_ELEMS / 4;
    convert_kernel<<<(n4 + 255) / 256, 256>>>(fm);

    dim3 grid(POOL, N_ROI);
    roi_pool_kernel<<<grid, 128>>>(rois, out);
}